// round 9
// baseline (speedup 1.0000x reference)
#include <cuda_runtime.h>

#define BB 8
#define HH 512
#define WW 512
#define BIGF 1.0e6f
#define BIG2 1.0e12f
#define NPIX (BB * HH * WW)          // 2097152
#define NGRP  16
#define KW    (HH / 32)              // 16 column-words per column
#define PAD   4
#define RPB   4                      // rows per block
#define TPR   128                    // threads per row (4 px/thread)
#define MAIN_GRID (BB * HH / RPB)    // 1024

__device__ unsigned int g_cbits[NGRP * KW * WW];   // column-packed bits, 512 KB
__device__ float        g_rowsum[2][BB * HH];
__device__ unsigned int g_maxbits[NGRP];
__device__ unsigned int g_counter = 0;

// fp32 max over a warp via integer redux (exact for non-negative floats).
__device__ __forceinline__ float redux_max_f32nn(float v) {
    unsigned r;
    asm("redux.sync.max.u32 %0, %1, 0xffffffff;" : "=r"(r) : "r"(__float_as_uint(v)));
    return __uint_as_float(r);
}

// Pass 1: pack masks into column words, vec4 I/O.
__global__ void k_bits(const float* __restrict__ out, const int* __restrict__ tgt) {
    __shared__ uint4 sh[128];
    int bi = blockIdx.x;              // [mb][hc] : 256 blocks
    if (bi == 0 && threadIdx.x < NGRP) g_maxbits[threadIdx.x] = 0u;

    int hc = bi & (KW - 1);
    int mb = bi >> 4;
    int m = mb >> 3, b = mb & 7;
    int vw   = threadIdx.x & 127;
    int half = threadIdx.x >> 7;
    int w  = vw << 2;
    int h0 = (hc << 5) + (half << 4);

    unsigned w0 = 0, w1 = 0, w2 = 0, w3 = 0;
    if (m == 0) {
        const int4* p = (const int4*)(tgt + (size_t)(b * HH + h0) * WW + w);
        #pragma unroll
        for (int hh = 0; hh < 16; ++hh) {
            int4 v = p[hh * (WW / 4)];
            unsigned s = (unsigned)((half << 4) + hh);
            w0 |= (unsigned)(v.x > 0) << s;  w1 |= (unsigned)(v.y > 0) << s;
            w2 |= (unsigned)(v.z > 0) << s;  w3 |= (unsigned)(v.w > 0) << s;
        }
    } else {
        const float4* p = (const float4*)(out + (size_t)((b * 2 + 1) * HH + h0) * WW + w);
        #pragma unroll
        for (int hh = 0; hh < 16; ++hh) {
            float4 v = p[hh * (WW / 4)];
            unsigned s = (unsigned)((half << 4) + hh);
            w0 |= (unsigned)(v.x > 0.5f) << s;  w1 |= (unsigned)(v.y > 0.5f) << s;
            w2 |= (unsigned)(v.z > 0.5f) << s;  w3 |= (unsigned)(v.w > 0.5f) << s;
        }
    }
    if (half == 0) sh[vw] = make_uint4(w0, w1, w2, w3);
    __syncthreads();
    if (half == 1) {
        uint4 o4 = sh[vw];
        ((uint4*)(g_cbits + (size_t)(mb * KW + hc) * WW))[vw] =
            make_uint4(w0 | o4.x, w1 | o4.y, w2 | o4.z, w3 | o4.w);
    }
}

// Fully general slow vertical distance (word-walk). Rare: distance > 32.
__device__ __noinline__ float vdist_slow(const unsigned* __restrict__ cb, unsigned c,
                                         int h, int k, unsigned o, int j) {
    float u;
    unsigned inv = ~c & ((o == 0) ? 0u : ((1u << o) - 1u));
    if (inv) {
        u = (float)((int)o - (31 - __clz(inv)));
    } else {
        int kk = k - 1; unsigned iv = 0;
        while (kk >= 0 && !(iv = ~cb[kk * WW + j])) --kk;
        u = (kk >= 0) ? (float)(h - (kk * 32 + 31 - __clz(iv)))
                      : (BIGF + (float)(h + 1));
    }
    float dn;
    unsigned inv2 = ~c & (0xFFFFFFFEu << o);
    if (inv2) {
        dn = (float)((__ffs(inv2) - 1) - (int)o);
    } else {
        int kk = k + 1; unsigned iv = 0;
        while (kk < KW && !(iv = ~cb[kk * WW + j])) ++kk;
        dn = (kk < KW) ? (float)(kk * 32 + __ffs(iv) - 1 - h)
                       : (BIGF + (float)(HH - h));
    }
    return fminf(u, dn);
}

// Branch-free vertical distance from a 64-bit window (covers >= +-32 rows);
// escapes to slow path with P ~ 2^-32 per pixel (also covers image edges).
__device__ __forceinline__ float vdist_fast(unsigned cu, unsigned c, unsigned cd,
                                            const unsigned* __restrict__ cb,
                                            int h, int k, unsigned o, int j) {
    if (!((c >> o) & 1u)) return 0.0f;
    unsigned long long u64 = ((unsigned long long)c  << 32) | (unsigned long long)cu;
    unsigned long long d64 = ((unsigned long long)cd << 32) | (unsigned long long)c;
    unsigned long long mu = ~u64 & ((1ULL << (32 + o)) - 1ULL);       // below center
    unsigned long long md = ~d64 & (0xFFFFFFFFFFFFFFFEULL << o);      // above center
    if (mu == 0ULL || md == 0ULL)
        return vdist_slow(cb, c, h, k, o, j);                         // rare
    float uu = (float)((int)(32 + o) - (63 - __clzll((long long)mu)));
    float dd = (float)(__ffsll((long long)md) - 1 - (int)o);
    return fminf(uu, dd);
}

// Straight-line exact envelope for 4 pixels (r<=4), no branches.
// Wn[0..11] = s[w0-4 .. w0+7]; pixel i centered at Wn[i+4].
__device__ __forceinline__ float env4_fast(const float* Wn, float* best) {
    float mx = 0.0f;
    #pragma unroll
    for (int i = 0; i < 4; ++i) {
        float bb = fminf(Wn[i + 4], BIG2);            // best0 = BIG*BIG clamp
        bb = fminf(bb, fminf(Wn[i + 3] + 1.0f,  Wn[i + 5] + 1.0f));
        bb = fminf(bb, fminf(Wn[i + 2] + 4.0f,  Wn[i + 6] + 4.0f));
        bb = fminf(bb, fminf(Wn[i + 1] + 9.0f,  Wn[i + 7] + 9.0f));
        bb = fminf(bb, fminf(Wn[i]     + 16.0f, Wn[i + 8] + 16.0f));
        best[i] = bb;
        mx = fmaxf(mx, bb);
    }
    return mx;
}

// Exact fallback for r>=5 (needs ~9-wide all-fg deep blob; p ~ 2^-54/pixel).
__device__ __noinline__ void env_fallback(const float* __restrict__ sprow,
                                          int w0, float* best) {
    #pragma unroll
    for (int i = 0; i < 4; ++i) {
        float bb = best[i];
        if (bb > 25.0f) {
            int p = w0 + i;
            for (int r = 5; r < WW; ++r) {
                float rr = (float)(r * r);            // integer-exact in fp32
                if (rr >= bb) break;                  // rigorous exact cutoff
                if (p >= r)     bb = fminf(bb, sprow[PAD + p - r] + rr);
                if (p + r < WW) bb = fminf(bb, sprow[PAD + p + r] + rr);
            }
            best[i] = bb;
        }
    }
}

// Pass 2: block = 4 rows x 128 threads, 4 px/thread, both masks; last block
// performs the tiny finalize.
__global__ void __launch_bounds__(RPB * TPR)
k_main(const float* __restrict__ out, float* __restrict__ res) {
    __shared__ __align__(16) float sp[RPB][2][PAD + WW + PAD];
    __shared__ float red[RPB][4][TPR / 32];
    __shared__ double part[16];
    __shared__ bool amLast;

    int tid = threadIdx.x;
    int grp = tid >> 7;                     // row group 0..3
    int t   = tid & (TPR - 1);              // 0..127
    int b   = blockIdx.x >> 7;              // 128 blocks per batch
    int h   = ((blockIdx.x & 127) << 2) + grp;
    int row = (b << 9) + h;
    int k = h >> 5;
    unsigned o = (unsigned)(h & 31);
    int w0 = t << 2;

    const unsigned* cbg = g_cbits + (size_t)b * KW * WW;        // gt
    const unsigned* cbs = g_cbits + (size_t)(8 + b) * KW * WW;  // seg
    const uint4 ONES = make_uint4(~0u, ~0u, ~0u, ~0u);

    if (t < PAD) {
        sp[grp][0][t] = BIG2; sp[grp][0][PAD + WW + t] = BIG2;
        sp[grp][1][t] = BIG2; sp[grp][1][PAD + WW + t] = BIG2;
    }

    uint4 cg4 = *(const uint4*)(cbg + k * WW + w0);             // kept for gtv
    float c0[4], c1[4];
    {
        uint4 cu4 = (k > 0)      ? *(const uint4*)(cbg + (k - 1) * WW + w0) : ONES;
        uint4 cd4 = (k < KW - 1) ? *(const uint4*)(cbg + (k + 1) * WW + w0) : ONES;
        unsigned cw[4] = {cg4.x, cg4.y, cg4.z, cg4.w};
        unsigned uw[4] = {cu4.x, cu4.y, cu4.z, cu4.w};
        unsigned dw[4] = {cd4.x, cd4.y, cd4.z, cd4.w};
        #pragma unroll
        for (int i = 0; i < 4; ++i) {
            float g = vdist_fast(uw[i], cw[i], dw[i], cbg, h, k, o, w0 + i);
            c0[i] = g * g;
        }
    }
    {
        uint4 cs4 = *(const uint4*)(cbs + k * WW + w0);
        uint4 cu4 = (k > 0)      ? *(const uint4*)(cbs + (k - 1) * WW + w0) : ONES;
        uint4 cd4 = (k < KW - 1) ? *(const uint4*)(cbs + (k + 1) * WW + w0) : ONES;
        unsigned cw[4] = {cs4.x, cs4.y, cs4.z, cs4.w};
        unsigned uw[4] = {cu4.x, cu4.y, cu4.z, cu4.w};
        unsigned dw[4] = {cd4.x, cd4.y, cd4.z, cd4.w};
        #pragma unroll
        for (int i = 0; i < 4; ++i) {
            float g = vdist_fast(uw[i], cw[i], dw[i], cbs, h, k, o, w0 + i);
            c1[i] = g * g;
        }
    }
    *(float4*)&sp[grp][0][PAD + w0] = make_float4(c0[0], c0[1], c0[2], c0[3]);
    *(float4*)&sp[grp][1][PAD + w0] = make_float4(c1[0], c1[1], c1[2], c1[3]);
    __syncthreads();

    float b0[4], b1[4];
    float needmax;
    {
        float4 L = *(const float4*)&sp[grp][0][w0];             // s[w0-4..w0-1]
        float4 R = *(const float4*)&sp[grp][0][PAD + w0 + 4];   // s[w0+4..w0+7]
        float Wn[12] = {L.x, L.y, L.z, L.w, c0[0], c0[1], c0[2], c0[3], R.x, R.y, R.z, R.w};
        needmax = env4_fast(Wn, b0);
    }
    {
        float4 L = *(const float4*)&sp[grp][1][w0];
        float4 R = *(const float4*)&sp[grp][1][PAD + w0 + 4];
        float Wn[12] = {L.x, L.y, L.z, L.w, c1[0], c1[1], c1[2], c1[3], R.x, R.y, R.z, R.w};
        needmax = fmaxf(needmax, env4_fast(Wn, b1));
    }
    if (needmax > 25.0f) {                    // single rare branch per thread
        env_fallback(sp[grp][0], w0, b0);
        env_fallback(sp[grp][1], w0, b1);
    }

    // loss: gt float == gt bit (target in {0,1})
    float4 sv = *(const float4*)(out + ((size_t)((b * 2 + 1) * HH + h)) * WW + w0);
    float segv[4] = {sv.x, sv.y, sv.z, sv.w};
    unsigned cw[4] = {cg4.x, cg4.y, cg4.z, cg4.w};
    float v0 = 0.0f, v1 = 0.0f, m0 = 0.0f, m1 = 0.0f;
    #pragma unroll
    for (int i = 0; i < 4; ++i) {
        float gtv = (float)((cw[i] >> o) & 1u);
        float d = segv[i] - gtv;
        float d2 = d * d;
        v0 += d2 * b0[i];  v1 += d2 * b1[i];
        m0 = fmaxf(m0, b0[i]);  m1 = fmaxf(m1, b1[i]);
    }

    // warp reduce: sums via shfl butterfly, maxes via integer redux
    #pragma unroll
    for (int ofs = 16; ofs > 0; ofs >>= 1) {
        v0 += __shfl_xor_sync(0xffffffffu, v0, ofs);
        v1 += __shfl_xor_sync(0xffffffffu, v1, ofs);
    }
    m0 = redux_max_f32nn(m0);
    m1 = redux_max_f32nn(m1);
    int wq = t >> 5;
    if ((t & 31) == 0) {
        red[grp][0][wq] = v0; red[grp][1][wq] = v1;
        red[grp][2][wq] = m0; red[grp][3][wq] = m1;
    }
    __syncthreads();
    if (t == 0) {
        float x0 = (red[grp][0][0] + red[grp][0][1]) + (red[grp][0][2] + red[grp][0][3]);
        float x1 = (red[grp][1][0] + red[grp][1][1]) + (red[grp][1][2] + red[grp][1][3]);
        float y0 = fmaxf(fmaxf(red[grp][2][0], red[grp][2][1]), fmaxf(red[grp][2][2], red[grp][2][3]));
        float y1 = fmaxf(fmaxf(red[grp][3][0], red[grp][3][1]), fmaxf(red[grp][3][2], red[grp][3][3]));
        g_rowsum[0][row] = x0;
        g_rowsum[1][row] = x1;
        atomicMax(&g_maxbits[b],     __float_as_uint(y0));
        atomicMax(&g_maxbits[8 + b], __float_as_uint(y1));
    }

    // ---- last-block finalize (deterministic: all inputs fully written) ----
    __threadfence();
    if (tid == 0) amLast = (atomicAdd(&g_counter, 1u) == MAIN_GRID - 1);
    __syncthreads();
    if (!amLast) return;

    int g = tid >> 5, l = tid & 31;       // 16 warps <-> 16 (mask,batch) groups
    if (g < 16) {
        int gm = g >> 3, gb = g & 7;
        double acc = 0.0;
        #pragma unroll
        for (int i = 0; i < 16; ++i)
            acc += (double)g_rowsum[gm][gb * HH + i * 32 + l];
        #pragma unroll
        for (int ofs = 16; ofs > 0; ofs >>= 1)
            acc += __shfl_xor_sync(0xffffffffu, acc, ofs);
        if (l == 0) {
            double mx = (double)fmaxf(__uint_as_float(g_maxbits[g]), 1.0f);
            part[g] = acc / mx;
        }
    }
    __syncthreads();
    if (tid == 0) {
        double total = 0.0;
        #pragma unroll
        for (int q = 0; q < 16; ++q) total += part[q];
        res[0] = (float)(total * (1.0 / (double)NPIX));
        g_counter = 0;                    // reset for next replay
    }
}

extern "C" void kernel_launch(void* const* d_in, const int* in_sizes, int n_in,
                              void* d_out, int out_size) {
    const float* out = (const float*)d_in[0];   // [8,2,512,512] float32
    const int*   tgt = (const int*)d_in[1];     // [8,1,512,512] int32

    k_bits<<<NGRP * KW, 256>>>(out, tgt);       // 256 blocks
    k_main<<<MAIN_GRID, RPB * TPR>>>(out, (float*)d_out);
}

// round 10
// speedup vs baseline: 1.1393x; 1.1393x over previous
#include <cuda_runtime.h>

#define BB 8
#define HH 512
#define WW 512
#define BIGF 1.0e6f
#define BIG2 1.0e12f
#define NPIX (BB * HH * WW)          // 2097152
#define NGRP  16
#define KW    (HH / 32)              // 16 column-words per column
#define PAD   4
#define RPB   4                      // rows per block
#define TPR   128                    // threads per row (4 px/thread)
#define MAIN_GRID (2 * BB * HH / RPB)   // 2048: one mask per block

__device__ unsigned int g_cbits[NGRP * KW * WW];   // column-packed bits, 512 KB
__device__ float        g_rowsum[2][BB * HH];
__device__ unsigned int g_maxbits[NGRP];
__device__ unsigned int g_counter = 0;

// fp32 max over a warp via integer redux (exact for non-negative floats).
__device__ __forceinline__ float redux_max_f32nn(float v) {
    unsigned r;
    asm("redux.sync.max.u32 %0, %1, 0xffffffff;" : "=r"(r) : "r"(__float_as_uint(v)));
    return __uint_as_float(r);
}

// Pass 1: pack masks into column words, vec4 I/O.
__global__ void k_bits(const float* __restrict__ out, const int* __restrict__ tgt) {
    __shared__ uint4 sh[128];
    int bi = blockIdx.x;              // [mb][hc] : 256 blocks
    if (bi == 0 && threadIdx.x < NGRP) g_maxbits[threadIdx.x] = 0u;

    int hc = bi & (KW - 1);
    int mb = bi >> 4;
    int m = mb >> 3, b = mb & 7;
    int vw   = threadIdx.x & 127;
    int half = threadIdx.x >> 7;
    int w  = vw << 2;
    int h0 = (hc << 5) + (half << 4);

    unsigned w0 = 0, w1 = 0, w2 = 0, w3 = 0;
    if (m == 0) {
        const int4* p = (const int4*)(tgt + (size_t)(b * HH + h0) * WW + w);
        #pragma unroll
        for (int hh = 0; hh < 16; ++hh) {
            int4 v = p[hh * (WW / 4)];
            unsigned s = (unsigned)((half << 4) + hh);
            w0 |= (unsigned)(v.x > 0) << s;  w1 |= (unsigned)(v.y > 0) << s;
            w2 |= (unsigned)(v.z > 0) << s;  w3 |= (unsigned)(v.w > 0) << s;
        }
    } else {
        const float4* p = (const float4*)(out + (size_t)((b * 2 + 1) * HH + h0) * WW + w);
        #pragma unroll
        for (int hh = 0; hh < 16; ++hh) {
            float4 v = p[hh * (WW / 4)];
            unsigned s = (unsigned)((half << 4) + hh);
            w0 |= (unsigned)(v.x > 0.5f) << s;  w1 |= (unsigned)(v.y > 0.5f) << s;
            w2 |= (unsigned)(v.z > 0.5f) << s;  w3 |= (unsigned)(v.w > 0.5f) << s;
        }
    }
    if (half == 0) sh[vw] = make_uint4(w0, w1, w2, w3);
    __syncthreads();
    if (half == 1) {
        uint4 o4 = sh[vw];
        ((uint4*)(g_cbits + (size_t)(mb * KW + hc) * WW))[vw] =
            make_uint4(w0 | o4.x, w1 | o4.y, w2 | o4.z, w3 | o4.w);
    }
}

// vertical 1D distance from column bits (exact equiv of BIG-init fw/bw scans)
__device__ __forceinline__ float vdist(const unsigned* __restrict__ cb, unsigned c,
                                       int h, int k, unsigned o, int j) {
    if (!((c >> o) & 1u)) return 0.0f;
    float u;
    unsigned inv = ~c & ((o == 0) ? 0u : ((1u << o) - 1u));
    if (inv) {
        u = (float)((int)o - (31 - __clz(inv)));
    } else {
        int kk = k - 1; unsigned iv = 0;
        while (kk >= 0 && !(iv = ~cb[kk * WW + j])) --kk;   // P~2^-32 per step
        u = (kk >= 0) ? (float)(h - (kk * 32 + 31 - __clz(iv)))
                      : (BIGF + (float)(h + 1));
    }
    float dn;
    unsigned inv2 = ~c & (0xFFFFFFFEu << o);
    if (inv2) {
        dn = (float)((__ffs(inv2) - 1) - (int)o);
    } else {
        int kk = k + 1; unsigned iv = 0;
        while (kk < KW && !(iv = ~cb[kk * WW + j])) ++kk;
        dn = (kk < KW) ? (float)(kk * 32 + __ffs(iv) - 1 - h)
                       : (BIGF + (float)(HH - h));
    }
    return fminf(u, dn);
}

// Straight-line exact envelope for 4 pixels (r<=4), no branches.
// Wn[0..11] = s[w0-4 .. w0+7]; pixel i centered at Wn[i+4].
__device__ __forceinline__ float env4_fast(const float* Wn, float* best) {
    float mx = 0.0f;
    #pragma unroll
    for (int i = 0; i < 4; ++i) {
        float bb = fminf(Wn[i + 4], BIG2);            // best0 = BIG*BIG clamp
        bb = fminf(bb, fminf(Wn[i + 3] + 1.0f,  Wn[i + 5] + 1.0f));
        bb = fminf(bb, fminf(Wn[i + 2] + 4.0f,  Wn[i + 6] + 4.0f));
        bb = fminf(bb, fminf(Wn[i + 1] + 9.0f,  Wn[i + 7] + 9.0f));
        bb = fminf(bb, fminf(Wn[i]     + 16.0f, Wn[i + 8] + 16.0f));
        best[i] = bb;
        mx = fmaxf(mx, bb);
    }
    return mx;
}

// Exact fallback for r>=5 (needs ~9-wide all-fg deep blob; p ~ 2^-54/pixel).
__device__ __noinline__ void env_fallback(const float* __restrict__ sprow,
                                          int w0, float* best) {
    #pragma unroll
    for (int i = 0; i < 4; ++i) {
        float bb = best[i];
        if (bb > 25.0f) {
            int p = w0 + i;
            for (int r = 5; r < WW; ++r) {
                float rr = (float)(r * r);            // integer-exact in fp32
                if (rr >= bb) break;                  // rigorous exact cutoff
                if (p >= r)     bb = fminf(bb, sprow[PAD + p - r] + rr);
                if (p + r < WW) bb = fminf(bb, sprow[PAD + p + r] + rr);
            }
            best[i] = bb;
        }
    }
}

// Pass 2: block = ONE mask x 4 rows x 128 threads (4 px/thread); last block
// performs the tiny finalize.
__global__ void __launch_bounds__(RPB * TPR)
k_main(const float* __restrict__ out, float* __restrict__ res) {
    __shared__ __align__(16) float sp[RPB][PAD + WW + PAD];
    __shared__ float red[RPB][2][TPR / 32];
    __shared__ double part[16];
    __shared__ bool amLast;

    int tid = threadIdx.x;
    int grp = tid >> 7;                     // row group 0..3
    int t   = tid & (TPR - 1);              // 0..127
    int m   = blockIdx.x >> 10;             // mask 0/1
    int rem = blockIdx.x & 1023;
    int b   = rem >> 7;                     // batch
    int h   = ((rem & 127) << 2) + grp;
    int row = (b << 9) + h;
    int k = h >> 5;
    unsigned o = (unsigned)(h & 31);
    int w0 = t << 2;

    const unsigned* cb  = g_cbits + (size_t)((m << 3) + b) * KW * WW;  // own mask
    const unsigned* cbg = g_cbits + (size_t)b * KW * WW;               // gt (m=0)

    if (t < PAD) { sp[grp][t] = BIG2; sp[grp][PAD + WW + t] = BIG2; }

    uint4 c4 = *(const uint4*)(cb + k * WW + w0);
    float c0[4];
    {
        unsigned cw[4] = {c4.x, c4.y, c4.z, c4.w};
        #pragma unroll
        for (int i = 0; i < 4; ++i) {
            float g = vdist(cb, cw[i], h, k, o, w0 + i);
            c0[i] = g * g;
        }
    }
    *(float4*)&sp[grp][PAD + w0] = make_float4(c0[0], c0[1], c0[2], c0[3]);
    __syncthreads();

    float b0[4];
    {
        float4 L = *(const float4*)&sp[grp][w0];              // s[w0-4..w0-1]
        float4 R = *(const float4*)&sp[grp][PAD + w0 + 4];    // s[w0+4..w0+7]
        float Wn[12] = {L.x, L.y, L.z, L.w, c0[0], c0[1], c0[2], c0[3], R.x, R.y, R.z, R.w};
        float needmax = env4_fast(Wn, b0);
        if (needmax > 25.0f)                 // single rare branch per thread
            env_fallback(sp[grp], w0, b0);
    }

    // loss: gt float == gt bit (target in {0,1})
    uint4 g4 = (m == 0) ? c4 : *(const uint4*)(cbg + k * WW + w0);
    float4 sv = *(const float4*)(out + ((size_t)((b * 2 + 1) * HH + h)) * WW + w0);
    float segv[4] = {sv.x, sv.y, sv.z, sv.w};
    unsigned gw[4] = {g4.x, g4.y, g4.z, g4.w};
    float v0 = 0.0f, m0 = 0.0f;
    #pragma unroll
    for (int i = 0; i < 4; ++i) {
        float gtv = (float)((gw[i] >> o) & 1u);
        float d = segv[i] - gtv;
        v0 += d * d * b0[i];
        m0 = fmaxf(m0, b0[i]);
    }

    // warp reduce: sum via shfl butterfly, max via integer redux
    #pragma unroll
    for (int ofs = 16; ofs > 0; ofs >>= 1)
        v0 += __shfl_xor_sync(0xffffffffu, v0, ofs);
    m0 = redux_max_f32nn(m0);
    int wq = t >> 5;
    if ((t & 31) == 0) { red[grp][0][wq] = v0; red[grp][1][wq] = m0; }
    __syncthreads();
    if (t == 0) {
        float x0 = (red[grp][0][0] + red[grp][0][1]) + (red[grp][0][2] + red[grp][0][3]);
        float y0 = fmaxf(fmaxf(red[grp][1][0], red[grp][1][1]),
                         fmaxf(red[grp][1][2], red[grp][1][3]));
        g_rowsum[m][row] = x0;
        atomicMax(&g_maxbits[(m << 3) + b], __float_as_uint(y0));
    }

    // ---- last-block finalize (deterministic: all inputs fully written) ----
    __threadfence();
    if (tid == 0) amLast = (atomicAdd(&g_counter, 1u) == MAIN_GRID - 1);
    __syncthreads();
    if (!amLast) return;

    int g = tid >> 5, l = tid & 31;       // 16 warps <-> 16 (mask,batch) groups
    if (g < 16) {
        int gm = g >> 3, gb = g & 7;
        double acc = 0.0;
        #pragma unroll
        for (int i = 0; i < 16; ++i)
            acc += (double)g_rowsum[gm][gb * HH + i * 32 + l];
        #pragma unroll
        for (int ofs = 16; ofs > 0; ofs >>= 1)
            acc += __shfl_xor_sync(0xffffffffu, acc, ofs);
        if (l == 0) {
            double mx = (double)fmaxf(__uint_as_float(g_maxbits[g]), 1.0f);
            part[g] = acc / mx;
        }
    }
    __syncthreads();
    if (tid == 0) {
        double total = 0.0;
        #pragma unroll
        for (int q = 0; q < 16; ++q) total += part[q];
        res[0] = (float)(total * (1.0 / (double)NPIX));
        g_counter = 0;                    // reset for next replay
    }
}

extern "C" void kernel_launch(void* const* d_in, const int* in_sizes, int n_in,
                              void* d_out, int out_size) {
    const float* out = (const float*)d_in[0];   // [8,2,512,512] float32
    const int*   tgt = (const int*)d_in[1];     // [8,1,512,512] int32

    k_bits<<<NGRP * KW, 256>>>(out, tgt);       // 256 blocks
    k_main<<<MAIN_GRID, RPB * TPR>>>(out, (float*)d_out);
}

// round 11
// speedup vs baseline: 1.2252x; 1.0755x over previous
#include <cuda_runtime.h>

#define BB 8
#define HH 512
#define WW 512
#define BIGF 1.0e6f
#define BIG2 1.0e12f
#define NPIX (BB * HH * WW)          // 2097152
#define NGRP  16
#define KW    (HH / 32)              // 16 word-rows
#define TILE  128                    // interior columns per block
#define NT    (WW / TILE)            // 4 tiles per row-band
#define TPB   128
#define MAIN_GRID (NGRP * KW * NT)   // 1024
#define SROW  136                    // 128 interior + 2*4 halo

__device__ unsigned g_cbits[NGRP * KW * WW];   // column-packed fg bits, 512 KB
__device__ float    g_blksum[MAIN_GRID];
__device__ unsigned g_maxbits[NGRP];
__device__ unsigned g_counter = 0;

__device__ __forceinline__ float redux_max_f32nn(float v) {
    unsigned r;
    asm("redux.sync.max.u32 %0, %1, 0xffffffff;" : "=r"(r) : "r"(__float_as_uint(v)));
    return __uint_as_float(r);
}

// Pass 1: pack masks into column words, vec4 I/O (measured ~1.5us).
__global__ void k_bits(const float* __restrict__ out, const int* __restrict__ tgt) {
    __shared__ uint4 sh[128];
    int bi = blockIdx.x;              // [mb][hc] : 256 blocks
    if (bi == 0 && threadIdx.x < NGRP) g_maxbits[threadIdx.x] = 0u;

    int hc = bi & (KW - 1);
    int mb = bi >> 4;
    int m = mb >> 3, b = mb & 7;
    int vw   = threadIdx.x & 127;
    int half = threadIdx.x >> 7;
    int w  = vw << 2;
    int h0 = (hc << 5) + (half << 4);

    unsigned w0 = 0, w1 = 0, w2 = 0, w3 = 0;
    if (m == 0) {
        const int4* p = (const int4*)(tgt + (size_t)(b * HH + h0) * WW + w);
        #pragma unroll
        for (int hh = 0; hh < 16; ++hh) {
            int4 v = p[hh * (WW / 4)];
            unsigned s = (unsigned)((half << 4) + hh);
            w0 |= (unsigned)(v.x > 0) << s;  w1 |= (unsigned)(v.y > 0) << s;
            w2 |= (unsigned)(v.z > 0) << s;  w3 |= (unsigned)(v.w > 0) << s;
        }
    } else {
        const float4* p = (const float4*)(out + (size_t)((b * 2 + 1) * HH + h0) * WW + w);
        #pragma unroll
        for (int hh = 0; hh < 16; ++hh) {
            float4 v = p[hh * (WW / 4)];
            unsigned s = (unsigned)((half << 4) + hh);
            w0 |= (unsigned)(v.x > 0.5f) << s;  w1 |= (unsigned)(v.y > 0.5f) << s;
            w2 |= (unsigned)(v.z > 0.5f) << s;  w3 |= (unsigned)(v.w > 0.5f) << s;
        }
    }
    if (half == 0) sh[vw] = make_uint4(w0, w1, w2, w3);
    __syncthreads();
    if (half == 1) {
        uint4 o4 = sh[vw];
        ((uint4*)(g_cbits + (size_t)(mb * KW + hc) * WW))[vw] =
            make_uint4(w0 | o4.x, w1 | o4.y, w2 | o4.z, w3 | o4.w);
    }
}

// Fully general vertical distance (word-walk). Rare path / fallback helper.
__device__ __noinline__ float vdist_slow(const unsigned* __restrict__ cb,
                                         unsigned c, int h, int k, unsigned o, int j) {
    float u;
    unsigned inv = ~c & ((o == 0) ? 0u : ((1u << o) - 1u));
    if (inv) {
        u = (float)((int)o - (31 - __clz(inv)));
    } else {
        int kk = k - 1; unsigned iv = 0;
        while (kk >= 0 && !(iv = ~cb[kk * WW + j])) --kk;
        u = (kk >= 0) ? (float)(h - (kk * 32 + 31 - __clz(iv)))
                      : (BIGF + (float)(h + 1));
    }
    float dn;
    unsigned inv2 = ~c & (0xFFFFFFFEu << o);
    if (inv2) {
        dn = (float)((__ffs(inv2) - 1) - (int)o);
    } else {
        int kk = k + 1; unsigned iv = 0;
        while (kk < KW && !(iv = ~cb[kk * WW + j])) ++kk;
        dn = (kk < KW) ? (float)(kk * 32 + __ffs(iv) - 1 - h)
                       : (BIGF + (float)(HH - h));
    }
    return fminf(u, dn);
}

// general g^2 at (h, col j) recomputed from global bits (exact).
__device__ float vdist2_g(const unsigned* __restrict__ cb, int h, int j) {
    int k = h >> 5; unsigned o = (unsigned)(h & 31);
    unsigned c = cb[k * WW + j];
    if (!((c >> o) & 1u)) return 0.0f;
    float g = vdist_slow(cb, c, h, k, o, j);
    return g * g;
}

// Straight-line exact envelope for 4 pixels (r<=4).
__device__ __forceinline__ float env4_fast(const float* Wn, float* best) {
    float mx = 0.0f;
    #pragma unroll
    for (int i = 0; i < 4; ++i) {
        float bb = fminf(Wn[i + 4], BIG2);            // best0 = BIG*BIG clamp
        bb = fminf(bb, fminf(Wn[i + 3] + 1.0f,  Wn[i + 5] + 1.0f));
        bb = fminf(bb, fminf(Wn[i + 2] + 4.0f,  Wn[i + 6] + 4.0f));
        bb = fminf(bb, fminf(Wn[i + 1] + 9.0f,  Wn[i + 7] + 9.0f));
        bb = fminf(bb, fminf(Wn[i]     + 16.0f, Wn[i + 8] + 16.0f));
        best[i] = bb;
        mx = fmaxf(mx, bb);
    }
    return mx;
}

// Exact fallback for r>=5 (p ~ 2^-54/pixel): recompute neighbor g^2 from bits.
__device__ __noinline__ void env_fallback_global(const unsigned* __restrict__ cb,
                                                 int h, int gc0, float* best) {
    #pragma unroll
    for (int i = 0; i < 4; ++i) {
        float bb = best[i];
        if (bb > 25.0f) {
            int p = gc0 + i;
            for (int r = 5; r < WW; ++r) {
                float rr = (float)(r * r);            // integer-exact in fp32
                if (rr >= bb) break;                  // rigorous exact cutoff
                if (p - r >= 0) bb = fminf(bb, vdist2_g(cb, h, p - r) + rr);
                if (p + r < WW) bb = fminf(bb, vdist2_g(cb, h, p + r) + rr);
            }
            best[i] = bb;
        }
    }
}

// per-column 32-bit window vdist: compute g^2 for bit o from precomputed
// complements nu (up window) / nd (down window); escapes with P~2^-32.
__device__ __forceinline__ float vdist2_bit(unsigned long long nu, unsigned long long nd,
                                            unsigned long long mku, unsigned long long mkd,
                                            unsigned c, const unsigned* __restrict__ cb,
                                            int k, int o, int gc) {
    if (!((c >> o) & 1u)) return 0.0f;
    unsigned long long mu = nu & mku;
    unsigned long long md = nd & mkd;
    if (mu && md) {
        int iu = (32 + o) - (63 - __clzll((long long)mu));
        int id = __ffsll((long long)md) - 1 - o;
        int gi = min(iu, id);
        return (float)(gi * gi);
    }
    float g = vdist_slow(cb, c, (k << 5) + o, k, (unsigned)o, gc);  // rare
    return g * g;
}

// Pass 2: band block = 32 rows x 128 cols (+8 halo), one mask; last block
// performs the tiny finalize.
__global__ void __launch_bounds__(TPB)
k_band(const float* __restrict__ out, float* __restrict__ res) {
    __shared__ __align__(16) float s[32][SROW];
    __shared__ float red[2][4];
    __shared__ double part[16];
    __shared__ bool amLast;

    int t = threadIdx.x;
    int bi = blockIdx.x;                 // [mb][k][tile]
    int tile0 = (bi & (NT - 1)) * TILE;
    int k  = (bi >> 2) & (KW - 1);
    int mb = bi >> 6;
    int m = mb >> 3, b = mb & 7;

    const unsigned* cb = g_cbits + (size_t)mb * KW * WW;

    // ---- phase 1a: vdist for own column (32 px) ----
    {
        int gc = tile0 + t;
        unsigned c  = cb[k * WW + gc];
        unsigned cu = (k > 0)      ? cb[(k - 1) * WW + gc] : 0xFFFFFFFFu;
        unsigned cd = (k < KW - 1) ? cb[(k + 1) * WW + gc] : 0xFFFFFFFFu;
        unsigned long long nu = ~((((unsigned long long)c)  << 32) | (unsigned long long)cu);
        unsigned long long nd = ~((((unsigned long long)cd) << 32) | (unsigned long long)c);
        unsigned long long mku = 0xFFFFFFFFULL;            // (1<<(32+o))-1, o=0
        unsigned long long mkd = 0xFFFFFFFFFFFFFFFEULL;    // ~0 << (o+1),  o=0
        float* sp = &s[0][t + 4];
        #pragma unroll 8
        for (int o = 0; o < 32; ++o) {
            *sp = vdist2_bit(nu, nd, mku, mkd, c, cb, k, o, gc);
            mku = (mku << 1) | 1ULL;
            mkd <<= 1;
            sp += SROW;
        }
    }
    // ---- phase 1b: halo columns (8 cols x 32 rows, 2 px/thread) ----
    {
        int ci = t >> 4;                  // 0..7
        int o2 = (t & 15) << 1;           // rows o2, o2+1
        int sidx = (ci < 4) ? ci : (132 + (ci - 4));
        int gc   = (ci < 4) ? (tile0 - 4 + ci) : (tile0 + 124 + ci);
        if (gc < 0 || gc >= WW) {
            s[o2][sidx] = BIG2; s[o2 + 1][sidx] = BIG2;
        } else {
            unsigned c  = cb[k * WW + gc];
            unsigned cu = (k > 0)      ? cb[(k - 1) * WW + gc] : 0xFFFFFFFFu;
            unsigned cd = (k < KW - 1) ? cb[(k + 1) * WW + gc] : 0xFFFFFFFFu;
            unsigned long long nu = ~((((unsigned long long)c)  << 32) | (unsigned long long)cu);
            unsigned long long nd = ~((((unsigned long long)cd) << 32) | (unsigned long long)c);
            #pragma unroll
            for (int q = 0; q < 2; ++q) {
                int o = o2 + q;
                unsigned long long mku = (o == 31) ? 0x7FFFFFFFFFFFFFFFULL
                                                   : ((1ULL << (32 + o)) - 1ULL);
                unsigned long long mkd = 0xFFFFFFFFFFFFFFFEULL << o;
                s[o][sidx] = vdist2_bit(nu, nd, mku, mkd, c, cb, k, o, gc);
            }
        }
    }
    __syncthreads();

    // ---- phase 2: envelope + loss over 32 rows x 128 cols ----
    int rq = t >> 5, tc = t & 31;
    int c0 = tc << 2;                     // interior col offset (0..124)
    const unsigned* cbg = g_cbits + (size_t)b * KW * WW;       // gt band
    uint4 gw4 = *(const uint4*)(cbg + k * WW + tile0 + c0);
    unsigned gw[4] = {gw4.x, gw4.y, gw4.z, gw4.w};

    float vacc = 0.0f, macc = 0.0f;
    #pragma unroll
    for (int it = 0; it < 8; ++it) {
        int r = (it << 2) + rq;
        const float* srow = s[r];
        float4 L = *(const float4*)&srow[c0];        // cols c0-4..c0-1
        float4 C = *(const float4*)&srow[c0 + 4];    // cols c0..c0+3
        float4 R = *(const float4*)&srow[c0 + 8];    // cols c0+4..c0+7
        float Wn[12] = {L.x, L.y, L.z, L.w, C.x, C.y, C.z, C.w, R.x, R.y, R.z, R.w};
        float b0[4];
        float needmax = env4_fast(Wn, b0);
        if (needmax > 25.0f)                          // essentially never
            env_fallback_global(cb, (k << 5) + r, tile0 + c0, b0);

        float4 sv = *(const float4*)(out +
            ((size_t)((b * 2 + 1) * HH + (k << 5) + r)) * WW + tile0 + c0);
        float sva[4] = {sv.x, sv.y, sv.z, sv.w};
        #pragma unroll
        for (int i = 0; i < 4; ++i) {
            float gtv = (float)((gw[i] >> r) & 1u);   // gt float == gt bit
            float d = sva[i] - gtv;
            vacc += d * d * b0[i];
            macc = fmaxf(macc, b0[i]);
        }
    }

    // ---- block reduce (4 warps) ----
    #pragma unroll
    for (int ofs = 16; ofs > 0; ofs >>= 1)
        vacc += __shfl_xor_sync(0xffffffffu, vacc, ofs);
    macc = redux_max_f32nn(macc);
    if ((t & 31) == 0) { red[0][rq] = vacc; red[1][rq] = macc; }
    __syncthreads();
    if (t == 0) {
        float x = (red[0][0] + red[0][1]) + (red[0][2] + red[0][3]);
        float y = fmaxf(fmaxf(red[1][0], red[1][1]), fmaxf(red[1][2], red[1][3]));
        g_blksum[bi] = x;
        atomicMax(&g_maxbits[mb], __float_as_uint(y));
    }

    // ---- last-block finalize ----
    __threadfence();
    if (t == 0) amLast = (atomicAdd(&g_counter, 1u) == MAIN_GRID - 1);
    __syncthreads();
    if (!amLast) return;

    int w = t >> 5, l = t & 31;           // 4 warps x 4 groups each
    #pragma unroll
    for (int q = 0; q < 4; ++q) {
        int g = (w << 2) + q;             // group = mb; 64 partials each
        double acc = (double)g_blksum[g * 64 + l] + (double)g_blksum[g * 64 + 32 + l];
        #pragma unroll
        for (int ofs = 16; ofs > 0; ofs >>= 1)
            acc += __shfl_xor_sync(0xffffffffu, acc, ofs);
        if (l == 0) {
            double mx = (double)fmaxf(__uint_as_float(g_maxbits[g]), 1.0f);
            part[g] = acc / mx;
        }
    }
    __syncthreads();
    if (t == 0) {
        double total = 0.0;
        #pragma unroll
        for (int q = 0; q < 16; ++q) total += part[q];
        res[0] = (float)(total * (1.0 / (double)NPIX));
        g_counter = 0;                    // reset for next replay
    }
}

extern "C" void kernel_launch(void* const* d_in, const int* in_sizes, int n_in,
                              void* d_out, int out_size) {
    const float* out = (const float*)d_in[0];   // [8,2,512,512] float32
    const int*   tgt = (const int*)d_in[1];     // [8,1,512,512] int32

    k_bits<<<NGRP * KW, 256>>>(out, tgt);       // 256 blocks
    k_band<<<MAIN_GRID, TPB>>>(out, (float*)d_out);
}